// round 2
// baseline (speedup 1.0000x reference)
#include <cuda_runtime.h>
#include <cstdint>

#define SQ 2048
#define SK 2048
#define DH 64
#define BQ 64
#define BK 64

__device__ __forceinline__ float ex2f(float x) {
    float r;
    asm("ex2.approx.f32 %0, %1;" : "=f"(r) : "f"(x));
    return r;
}

__global__ void __launch_bounds__(256, 2)
fa_kernel(const float* __restrict__ Q, const float* __restrict__ K,
          const float* __restrict__ V, const int* __restrict__ VL,
          float* __restrict__ O)
{
    extern __shared__ float sm[];
    float* Qs = sm;                        // [64 row][64 d]
    float* Kt = sm + BQ * DH;              // [64 d][64 key], XOR-swizzled; reused as P [64 row][64 key]
    float* Vs = sm + BQ * DH + DH * BK;    // [64 key][64 d]

    const int b   = blockIdx.y;
    const int q0  = blockIdx.x * BQ;
    const int tid = threadIdx.x;
    const int tx  = tid & 15;
    const int ty  = tid >> 4;
    const int r0  = ty << 2;
    const int c0  = tx << 2;
    const int valid = VL[b];

    const float* Qb = Q + ((size_t)b * SQ + q0) * DH;
    const float* Kb = K + (size_t)b * SK * DH;
    const float* Vb = V + (size_t)b * SK * DH;
    float*       Ob = O + ((size_t)b * SQ + q0) * DH;

    // fold 1/sqrt(D) and log2(e) into Q so softmax uses exp2 directly
    const float qscale = 1.4426950408889634f / 8.0f;

    #pragma unroll
    for (int it = 0; it < 4; it++) {
        int idx = tid + it * 256;          // 1024 float4 slots = 64x64
        int row = idx >> 4;
        int cc  = (idx & 15) << 2;
        float4 qv = *(const float4*)(Qb + row * DH + cc);
        qv.x *= qscale; qv.y *= qscale; qv.z *= qscale; qv.w *= qscale;
        *(float4*)(Qs + row * DH + cc) = qv;
    }

    float m[4], l[4], acc[4][4];
    #pragma unroll
    for (int i = 0; i < 4; i++) {
        m[i] = -1e30f; l[i] = 0.f;
        #pragma unroll
        for (int j = 0; j < 4; j++) acc[i][j] = 0.f;
    }

    // Only iterate over valid key tiles: exp2(-1e6-ish) == 0 exactly,
    // so skipping fully-masked tiles is mathematically exact.
    const int ntiles = (valid + BK - 1) >> 6;

    for (int kt = 0; kt < ntiles; kt++) {
        const int k0 = kt << 6;

        // Load K (transposed + swizzled) and V tiles
        #pragma unroll
        for (int it = 0; it < 4; it++) {
            int idx = tid + it * 256;
            int key = idx >> 4;
            int c4  = idx & 15;
            int d   = c4 << 2;
            float4 kv = *(const float4*)(Kb + (size_t)(k0 + key) * DH + d);
            int sk = key ^ ((c4 & 7) << 2);       // XOR swizzle on 4-float groups
            Kt[(d + 0) * BK + sk] = kv.x;
            Kt[(d + 1) * BK + sk] = kv.y;
            Kt[(d + 2) * BK + sk] = kv.z;
            Kt[(d + 3) * BK + sk] = kv.w;
            float4 vv = *(const float4*)(Vb + (size_t)(k0 + key) * DH + d);
            *(float4*)(Vs + key * DH + d) = vv;
        }
        __syncthreads();

        // ---- GEMM1: S[64x64] = Qs @ K^T ----
        float s[4][4];
        #pragma unroll
        for (int i = 0; i < 4; i++)
            #pragma unroll
            for (int j = 0; j < 4; j++) s[i][j] = 0.f;

        #pragma unroll 4
        for (int d0 = 0; d0 < DH; d0 += 4) {
            float4 af[4], bf[4];
            int swz = ((d0 >> 2) & 7) << 2;
            #pragma unroll
            for (int i = 0; i < 4; i++)
                af[i] = *(const float4*)(Qs + (r0 + i) * DH + d0);
            #pragma unroll
            for (int dd = 0; dd < 4; dd++)
                bf[dd] = *(const float4*)(Kt + (d0 + dd) * BK + (c0 ^ swz));
            #pragma unroll
            for (int i = 0; i < 4; i++) {
                const float* ai = (const float*)&af[i];
                #pragma unroll
                for (int dd = 0; dd < 4; dd++) {
                    const float* bd = (const float*)&bf[dd];
                    float a = ai[dd];
                    #pragma unroll
                    for (int j = 0; j < 4; j++)
                        s[i][j] = fmaf(a, bd[j], s[i][j]);
                }
            }
        }

        // Mask tail keys of the last (partial) tile
        if (k0 + BK > valid) {
            #pragma unroll
            for (int j = 0; j < 4; j++) {
                if (k0 + c0 + j >= valid) {
                    #pragma unroll
                    for (int i = 0; i < 4; i++) s[i][j] = -1e30f;
                }
            }
        }

        // ---- Online softmax (rows split across 16 lanes) ----
        #pragma unroll
        for (int i = 0; i < 4; i++) {
            float rm = fmaxf(fmaxf(s[i][0], s[i][1]), fmaxf(s[i][2], s[i][3]));
            rm = fmaxf(rm, __shfl_xor_sync(0xffffffffu, rm, 1));
            rm = fmaxf(rm, __shfl_xor_sync(0xffffffffu, rm, 2));
            rm = fmaxf(rm, __shfl_xor_sync(0xffffffffu, rm, 4));
            rm = fmaxf(rm, __shfl_xor_sync(0xffffffffu, rm, 8));
            float mn   = fmaxf(m[i], rm);
            float corr = ex2f(m[i] - mn);
            float rs = 0.f;
            #pragma unroll
            for (int j = 0; j < 4; j++) {
                float p = ex2f(s[i][j] - mn);
                s[i][j] = p;
                rs += p;
            }
            rs += __shfl_xor_sync(0xffffffffu, rs, 1);
            rs += __shfl_xor_sync(0xffffffffu, rs, 2);
            rs += __shfl_xor_sync(0xffffffffu, rs, 4);
            rs += __shfl_xor_sync(0xffffffffu, rs, 8);
            l[i] = l[i] * corr + rs;
            m[i] = mn;
            #pragma unroll
            for (int j = 0; j < 4; j++) acc[i][j] *= corr;
        }

        __syncthreads();   // everyone done reading Kt before it becomes P
        #pragma unroll
        for (int i = 0; i < 4; i++)
            *(float4*)(Kt + (r0 + i) * BK + c0) =
                make_float4(s[i][0], s[i][1], s[i][2], s[i][3]);
        __syncthreads();

        // ---- GEMM2: acc += P @ V ----
        #pragma unroll 4
        for (int n0 = 0; n0 < BK; n0 += 4) {
            float4 pf[4], vf[4];
            #pragma unroll
            for (int i = 0; i < 4; i++)
                pf[i] = *(const float4*)(Kt + (r0 + i) * BK + n0);
            #pragma unroll
            for (int nn = 0; nn < 4; nn++)
                vf[nn] = *(const float4*)(Vs + (n0 + nn) * DH + c0);
            #pragma unroll
            for (int i = 0; i < 4; i++) {
                const float* pi = (const float*)&pf[i];
                #pragma unroll
                for (int nn = 0; nn < 4; nn++) {
                    const float* vn = (const float*)&vf[nn];
                    float p = pi[nn];
                    #pragma unroll
                    for (int j = 0; j < 4; j++)
                        acc[i][j] = fmaf(p, vn[j], acc[i][j]);
                }
            }
        }
        __syncthreads();   // before next tile overwrites Kt/Vs
    }

    #pragma unroll
    for (int i = 0; i < 4; i++) {
        float inv = 1.0f / l[i];
        *(float4*)(Ob + (r0 + i) * DH + c0) =
            make_float4(acc[i][0] * inv, acc[i][1] * inv,
                        acc[i][2] * inv, acc[i][3] * inv);
    }
}

extern "C" void kernel_launch(void* const* d_in, const int* in_sizes, int n_in,
                              void* d_out, int out_size) {
    const float* Q  = (const float*)d_in[0];
    const float* K  = (const float*)d_in[1];
    const float* V  = (const float*)d_in[2];
    const int*   VL = (const int*)d_in[3];
    float*       O  = (float*)d_out;

    const int B = in_sizes[3];             // number of batches = len(valid_lens)
    const int smem = (BQ * DH + DH * BK + BK * DH) * (int)sizeof(float); // 49152

    cudaFuncSetAttribute(fa_kernel, cudaFuncAttributeMaxDynamicSharedMemorySize, smem);
    dim3 grid(SQ / BQ, B);
    fa_kernel<<<grid, 256, smem>>>(Q, K, V, VL, O);
}

// round 3
// speedup vs baseline: 1.0074x; 1.0074x over previous
#include <cuda_runtime.h>
#include <cstdint>

#define SQ 2048
#define SK 2048
#define DH 64
#define BQ 64
#define BK 64

__device__ __forceinline__ float ex2f(float x) {
    float r;
    asm("ex2.approx.f32 %0, %1;" : "=f"(r) : "f"(x));
    return r;
}

__global__ void __launch_bounds__(256, 2)
fa_kernel(const float* __restrict__ Q, const float* __restrict__ K,
          const float* __restrict__ V, const int* __restrict__ VL,
          float* __restrict__ O)
{
    extern __shared__ float sm[];
    float* Qs = sm;                        // [64 row][64 d]
    float* Kt = sm + BQ * DH;              // [64 d][64 key], XOR-swizzled; reused as P [64 row][64 key]
    float* Vs = sm + BQ * DH + DH * BK;    // [64 key][64 d]

    const int b   = blockIdx.y;
    const int q0  = blockIdx.x * BQ;
    const int tid = threadIdx.x;
    const int tx  = tid & 15;
    const int ty  = tid >> 4;
    const int r0  = ty << 2;
    const int c0  = tx << 2;
    const int valid = VL[b];

    const float* Qb = Q + ((size_t)b * SQ + q0) * DH;
    const float* Kb = K + (size_t)b * SK * DH;
    const float* Vb = V + (size_t)b * SK * DH;
    float*       Ob = O + ((size_t)b * SQ + q0) * DH;

    // fold 1/sqrt(D) and log2(e) into Q so softmax uses exp2 directly
    const float qscale = 1.4426950408889634f / 8.0f;

    #pragma unroll
    for (int it = 0; it < 4; it++) {
        int idx = tid + it * 256;          // 1024 float4 slots = 64x64
        int row = idx >> 4;
        int cc  = (idx & 15) << 2;
        float4 qv = *(const float4*)(Qb + row * DH + cc);
        qv.x *= qscale; qv.y *= qscale; qv.z *= qscale; qv.w *= qscale;
        *(float4*)(Qs + row * DH + cc) = qv;
    }

    float m[4], l[4], acc[4][4];
    #pragma unroll
    for (int i = 0; i < 4; i++) {
        m[i] = -1e30f; l[i] = 0.f;
        #pragma unroll
        for (int j = 0; j < 4; j++) acc[i][j] = 0.f;
    }

    // Only iterate over valid key tiles: exp2(-1e6-ish) == 0 exactly,
    // so skipping fully-masked tiles is mathematically exact.
    const int ntiles = (valid + BK - 1) >> 6;

    for (int kt = 0; kt < ntiles; kt++) {
        const int k0 = kt << 6;

        // Load K (transposed + swizzled) and V tiles
        #pragma unroll
        for (int it = 0; it < 4; it++) {
            int idx = tid + it * 256;
            int key = idx >> 4;
            int c4  = idx & 15;
            int d   = c4 << 2;
            float4 kv = *(const float4*)(Kb + (size_t)(k0 + key) * DH + d);
            int sk = key ^ ((c4 & 7) << 2);       // XOR swizzle on 4-float groups
            Kt[(d + 0) * BK + sk] = kv.x;
            Kt[(d + 1) * BK + sk] = kv.y;
            Kt[(d + 2) * BK + sk] = kv.z;
            Kt[(d + 3) * BK + sk] = kv.w;
            float4 vv = *(const float4*)(Vb + (size_t)(k0 + key) * DH + d);
            *(float4*)(Vs + key * DH + d) = vv;
        }
        __syncthreads();

        // ---- GEMM1: S[64x64] = Qs @ K^T ----
        float s[4][4];
        #pragma unroll
        for (int i = 0; i < 4; i++)
            #pragma unroll
            for (int j = 0; j < 4; j++) s[i][j] = 0.f;

        #pragma unroll 4
        for (int d0 = 0; d0 < DH; d0 += 4) {
            float4 af[4], bf[4];
            int swz = ((d0 >> 2) & 7) << 2;
            #pragma unroll
            for (int i = 0; i < 4; i++)
                af[i] = *(const float4*)(Qs + (r0 + i) * DH + d0);
            #pragma unroll
            for (int dd = 0; dd < 4; dd++)
                bf[dd] = *(const float4*)(Kt + (d0 + dd) * BK + (c0 ^ swz));
            #pragma unroll
            for (int i = 0; i < 4; i++) {
                const float* ai = (const float*)&af[i];
                #pragma unroll
                for (int dd = 0; dd < 4; dd++) {
                    const float* bd = (const float*)&bf[dd];
                    float a = ai[dd];
                    #pragma unroll
                    for (int j = 0; j < 4; j++)
                        s[i][j] = fmaf(a, bd[j], s[i][j]);
                }
            }
        }

        // Mask tail keys of the last (partial) tile
        if (k0 + BK > valid) {
            #pragma unroll
            for (int j = 0; j < 4; j++) {
                if (k0 + c0 + j >= valid) {
                    #pragma unroll
                    for (int i = 0; i < 4; i++) s[i][j] = -1e30f;
                }
            }
        }

        // ---- Online softmax (rows split across 16 lanes) ----
        #pragma unroll
        for (int i = 0; i < 4; i++) {
            float rm = fmaxf(fmaxf(s[i][0], s[i][1]), fmaxf(s[i][2], s[i][3]));
            rm = fmaxf(rm, __shfl_xor_sync(0xffffffffu, rm, 1));
            rm = fmaxf(rm, __shfl_xor_sync(0xffffffffu, rm, 2));
            rm = fmaxf(rm, __shfl_xor_sync(0xffffffffu, rm, 4));
            rm = fmaxf(rm, __shfl_xor_sync(0xffffffffu, rm, 8));
            float mn   = fmaxf(m[i], rm);
            float corr = ex2f(m[i] - mn);
            float rs = 0.f;
            #pragma unroll
            for (int j = 0; j < 4; j++) {
                float p = ex2f(s[i][j] - mn);
                s[i][j] = p;
                rs += p;
            }
            rs += __shfl_xor_sync(0xffffffffu, rs, 1);
            rs += __shfl_xor_sync(0xffffffffu, rs, 2);
            rs += __shfl_xor_sync(0xffffffffu, rs, 4);
            rs += __shfl_xor_sync(0xffffffffu, rs, 8);
            l[i] = l[i] * corr + rs;
            m[i] = mn;
            #pragma unroll
            for (int j = 0; j < 4; j++) acc[i][j] *= corr;
        }

        __syncthreads();   // everyone done reading Kt before it becomes P
        #pragma unroll
        for (int i = 0; i < 4; i++)
            *(float4*)(Kt + (r0 + i) * BK + c0) =
                make_float4(s[i][0], s[i][1], s[i][2], s[i][3]);
        __syncthreads();

        // ---- GEMM2: acc += P @ V ----
        #pragma unroll 4
        for (int n0 = 0; n0 < BK; n0 += 4) {
            float4 pf[4], vf[4];
            #pragma unroll
            for (int i = 0; i < 4; i++)
                pf[i] = *(const float4*)(Kt + (r0 + i) * BK + n0);
            #pragma unroll
            for (int nn = 0; nn < 4; nn++)
                vf[nn] = *(const float4*)(Vs + (n0 + nn) * DH + c0);
            #pragma unroll
            for (int i = 0; i < 4; i++) {
                const float* pi = (const float*)&pf[i];
                #pragma unroll
                for (int nn = 0; nn < 4; nn++) {
                    const float* vn = (const float*)&vf[nn];
                    float p = pi[nn];
                    #pragma unroll
                    for (int j = 0; j < 4; j++)
                        acc[i][j] = fmaf(p, vn[j], acc[i][j]);
                }
            }
        }
        __syncthreads();   // before next tile overwrites Kt/Vs
    }

    #pragma unroll
    for (int i = 0; i < 4; i++) {
        float inv = 1.0f / l[i];
        *(float4*)(Ob + (r0 + i) * DH + c0) =
            make_float4(acc[i][0] * inv, acc[i][1] * inv,
                        acc[i][2] * inv, acc[i][3] * inv);
    }
}

extern "C" void kernel_launch(void* const* d_in, const int* in_sizes, int n_in,
                              void* d_out, int out_size) {
    const float* Q  = (const float*)d_in[0];
    const float* K  = (const float*)d_in[1];
    const float* V  = (const float*)d_in[2];
    const int*   VL = (const int*)d_in[3];
    float*       O  = (float*)d_out;

    const int B = in_sizes[3];             // number of batches = len(valid_lens)
    const int smem = (BQ * DH + DH * BK + BK * DH) * (int)sizeof(float); // 49152

    cudaFuncSetAttribute(fa_kernel, cudaFuncAttributeMaxDynamicSharedMemorySize, smem);
    dim3 grid(SQ / BQ, B);
    fa_kernel<<<grid, 256, smem>>>(Q, K, V, VL, O);
}

// round 5
// speedup vs baseline: 2.7795x; 2.7591x over previous
#include <cuda_runtime.h>
#include <cuda_bf16.h>
#include <cstdint>

#define SQ 2048
#define DH 64
#define BQ 128
#define BK 64
#define LDB 144          // smem row stride in bytes (72 bf16) -> conflict-free ldmatrix

// smem byte offsets (one 36 KB region; Q staging overlaps K/V)
#define OFF_KHI 0
#define OFF_KLO 9216
#define OFF_VHI 18432
#define OFF_VLO 27648
#define OFF_QHI 0        // Q staging: 128 rows * 144B = 18432 (hi), then lo
#define OFF_QLO 18432
#define SMEM_SZ 36864

__device__ __forceinline__ float ex2f(float x) {
    float r; asm("ex2.approx.f32 %0, %1;" : "=f"(r) : "f"(x)); return r;
}
__device__ __forceinline__ uint32_t smem_u32(const void* p) {
    uint32_t a;
    asm("{ .reg .u64 t; cvta.to.shared.u64 t, %1; cvt.u32.u64 %0, t; }" : "=r"(a) : "l"(p));
    return a;
}
// split two fp32 into packed bf16 hi + bf16 lo residual (elem0 in low half)
__device__ __forceinline__ void bfsplit2(float x0, float x1, uint32_t& hp, uint32_t& lp) {
    asm("cvt.rn.bf16x2.f32 %0, %1, %2;" : "=r"(hp) : "f"(x1), "f"(x0));
    float h0 = __uint_as_float(hp << 16);
    float h1 = __uint_as_float(hp & 0xffff0000u);
    asm("cvt.rn.bf16x2.f32 %0, %1, %2;" : "=r"(lp) : "f"(x1 - h1), "f"(x0 - h0));
}
__device__ __forceinline__ void ldsm4(uint32_t a, uint32_t* r) {
    asm volatile("ldmatrix.sync.aligned.m8n8.x4.shared.b16 {%0,%1,%2,%3}, [%4];"
                 : "=r"(r[0]), "=r"(r[1]), "=r"(r[2]), "=r"(r[3]) : "r"(a));
}
__device__ __forceinline__ void ldsm4t(uint32_t a, uint32_t* r) {
    asm volatile("ldmatrix.sync.aligned.m8n8.x4.trans.shared.b16 {%0,%1,%2,%3}, [%4];"
                 : "=r"(r[0]), "=r"(r[1]), "=r"(r[2]), "=r"(r[3]) : "r"(a));
}
__device__ __forceinline__ void mma16816(float* d, const uint32_t* a, const uint32_t* b) {
    asm volatile("mma.sync.aligned.m16n8k16.row.col.f32.bf16.bf16.f32 "
                 "{%0,%1,%2,%3}, {%4,%5,%6,%7}, {%8,%9}, {%0,%1,%2,%3};"
                 : "+f"(d[0]), "+f"(d[1]), "+f"(d[2]), "+f"(d[3])
                 : "r"(a[0]), "r"(a[1]), "r"(a[2]), "r"(a[3]), "r"(b[0]), "r"(b[1]));
}

__global__ void __launch_bounds__(256)
fa_hmma(const float* __restrict__ Q, const float* __restrict__ K,
        const float* __restrict__ V, const int* __restrict__ VL,
        float* __restrict__ O)
{
    __shared__ __align__(128) char smc[SMEM_SZ];
    const uint32_t sb = smem_u32(smc);

    const int tid  = threadIdx.x;
    const int wid  = tid >> 5;
    const int lane = tid & 31;
    const int b    = blockIdx.y;
    const int q0   = blockIdx.x * BQ;
    const int valid = VL[b];

    const float* Qb = Q + ((size_t)b * SQ + q0) * DH;
    const float* Kb = K + (size_t)b * SQ * DH;
    const float* Vb = V + (size_t)b * SQ * DH;
    float*       Ob = O + ((size_t)b * SQ + q0) * DH;

    // ---- stage Q (scaled by log2e/sqrt(D)), split hi/lo into smem ----
    const float qs = 1.4426950408889634f / 8.0f;
    #pragma unroll
    for (int it = 0; it < 8; it++) {
        int idx = tid + (it << 8);              // 2048 float4 slots = 128x64
        int r = idx >> 4, d4 = (idx & 15) << 2;
        float4 qv = *(const float4*)(Qb + r * DH + d4);
        uint32_t h01, l01, h23, l23;
        bfsplit2(qv.x * qs, qv.y * qs, h01, l01);
        bfsplit2(qv.z * qs, qv.w * qs, h23, l23);
        uint32_t off = (uint32_t)(r * LDB + (d4 << 1));
        *(uint2*)(smc + OFF_QHI + off) = make_uint2(h01, h23);
        *(uint2*)(smc + OFF_QLO + off) = make_uint2(l01, l23);
    }
    __syncthreads();

    // ---- Q fragments into registers (A operand, m16 rows per warp) ----
    uint32_t qh[4][4], ql[4][4];
    {
        int row = wid * 16 + (lane & 15);
        int cb  = (lane >> 4) << 3;             // +0 or +8 cols
        #pragma unroll
        for (int kt4 = 0; kt4 < 4; kt4++) {
            uint32_t a = sb + (uint32_t)(row * LDB + ((kt4 * 16 + cb) << 1));
            ldsm4(a + OFF_QHI, qh[kt4]);
            ldsm4(a + OFF_QLO, ql[kt4]);
        }
    }

    float oacc[8][4];
    #pragma unroll
    for (int j = 0; j < 8; j++)
        #pragma unroll
        for (int i = 0; i < 4; i++) oacc[j][i] = 0.f;
    float ls0 = 0.f, ls1 = 0.f;

    const int ntiles = (valid + BK - 1) >> 6;   // masked tiles contribute exactly 0

    for (int kt = 0; kt < ntiles; kt++) {
        const int k0 = kt << 6;
        __syncthreads();                        // prior tile's smem reads done

        // ---- load K,V tile (64x64 fp32), split hi/lo into smem ----
        #pragma unroll
        for (int it = 0; it < 4; it++) {
            int idx = tid + (it << 8);          // 1024 float4 slots = 64x64
            int r = idx >> 4, d4 = (idx & 15) << 2;
            uint32_t off = (uint32_t)(r * LDB + (d4 << 1));
            float4 kv = *(const float4*)(Kb + (size_t)(k0 + r) * DH + d4);
            uint32_t h01, l01, h23, l23;
            bfsplit2(kv.x, kv.y, h01, l01); bfsplit2(kv.z, kv.w, h23, l23);
            *(uint2*)(smc + OFF_KHI + off) = make_uint2(h01, h23);
            *(uint2*)(smc + OFF_KLO + off) = make_uint2(l01, l23);
            float4 vv = *(const float4*)(Vb + (size_t)(k0 + r) * DH + d4);
            bfsplit2(vv.x, vv.y, h01, l01); bfsplit2(vv.z, vv.w, h23, l23);
            *(uint2*)(smc + OFF_VHI + off) = make_uint2(h01, h23);
            *(uint2*)(smc + OFF_VLO + off) = make_uint2(l01, l23);
        }
        __syncthreads();

        // ---- GEMM1: S = Qhi*Khi + Qhi*Klo + Qlo*Khi ----
        float sacc[8][4];
        #pragma unroll
        for (int j = 0; j < 8; j++) {
            #pragma unroll
            for (int i = 0; i < 4; i++) sacc[j][i] = 0.f;
            uint32_t kh[8], kl[8];
            uint32_t a = sb + (uint32_t)((j * 8 + (lane & 7)) * LDB + (((lane >> 3) << 3) << 1));
            ldsm4(a + OFF_KHI, kh); ldsm4(a + OFF_KHI + 64, kh + 4);
            ldsm4(a + OFF_KLO, kl); ldsm4(a + OFF_KLO + 64, kl + 4);
            #pragma unroll
            for (int kt4 = 0; kt4 < 4; kt4++) mma16816(sacc[j], qh[kt4], kh + 2 * kt4);
            #pragma unroll
            for (int kt4 = 0; kt4 < 4; kt4++) mma16816(sacc[j], qh[kt4], kl + 2 * kt4);
            #pragma unroll
            for (int kt4 = 0; kt4 < 4; kt4++) mma16816(sacc[j], ql[kt4], kh + 2 * kt4);
        }

        // ---- exp2 + mask + convert P to bf16 hi/lo (register-only) ----
        const bool full = (k0 + BK <= valid);
        uint32_t ph[8][2], pl[8][2];
        #pragma unroll
        for (int j = 0; j < 8; j++) {
            float p0 = ex2f(sacc[j][0]), p1 = ex2f(sacc[j][1]);
            float p2 = ex2f(sacc[j][2]), p3 = ex2f(sacc[j][3]);
            if (!full) {
                int key0 = k0 + j * 8 + ((lane & 3) << 1);
                if (key0     >= valid) { p0 = 0.f; p2 = 0.f; }
                if (key0 + 1 >= valid) { p1 = 0.f; p3 = 0.f; }
            }
            ls0 += p0 + p1; ls1 += p2 + p3;
            bfsplit2(p0, p1, ph[j][0], pl[j][0]);
            bfsplit2(p2, p3, ph[j][1], pl[j][1]);
        }

        // ---- GEMM2: O += Phi*Vhi + Phi*Vlo + Plo*Vhi ----
        #pragma unroll
        for (int t = 0; t < 4; t++) {
            uint32_t Ah[4] = { ph[2*t][0], ph[2*t][1], ph[2*t+1][0], ph[2*t+1][1] };
            uint32_t Al[4] = { pl[2*t][0], pl[2*t][1], pl[2*t+1][0], pl[2*t+1][1] };
            int vrow = t * 16 + (((lane >> 3) & 1) << 3) + (lane & 7);
            #pragma unroll
            for (int j2 = 0; j2 < 4; j2++) {
                uint32_t vh[4], vl4[4];
                uint32_t a = sb + (uint32_t)(vrow * LDB + ((j2 * 16 + ((lane >> 4) << 3)) << 1));
                ldsm4t(a + OFF_VHI, vh);
                ldsm4t(a + OFF_VLO, vl4);
                mma16816(oacc[2*j2],     Ah, vh);
                mma16816(oacc[2*j2],     Ah, vl4);
                mma16816(oacc[2*j2],     Al, vh);
                mma16816(oacc[2*j2 + 1], Ah, vh + 2);
                mma16816(oacc[2*j2 + 1], Ah, vl4 + 2);
                mma16816(oacc[2*j2 + 1], Al, vh + 2);
            }
        }
    }

    // ---- reduce l across the 4 lanes sharing each row, normalize, store ----
    ls0 += __shfl_xor_sync(0xffffffffu, ls0, 1);
    ls0 += __shfl_xor_sync(0xffffffffu, ls0, 2);
    ls1 += __shfl_xor_sync(0xffffffffu, ls1, 1);
    ls1 += __shfl_xor_sync(0xffffffffu, ls1, 2);
    float inv0 = 1.0f / ls0, inv1 = 1.0f / ls1;

    int g = lane >> 2, c = lane & 3;
    float* r0p = Ob + (wid * 16 + g) * DH;
    float* r1p = r0p + 8 * DH;
    #pragma unroll
    for (int j = 0; j < 8; j++) {
        int col = j * 8 + 2 * c;
        *(float2*)(r0p + col) = make_float2(oacc[j][0] * inv0, oacc[j][1] * inv0);
        *(float2*)(r1p + col) = make_float2(oacc[j][2] * inv1, oacc[j][3] * inv1);
    }
}

extern "C" void kernel_launch(void* const* d_in, const int* in_sizes, int n_in,
                              void* d_out, int out_size) {
    const float* Q  = (const float*)d_in[0];
    const float* K  = (const float*)d_in[1];
    const float* V  = (const float*)d_in[2];
    const int*   VL = (const int*)d_in[3];
    float*       O  = (float*)d_out;
    const int B = in_sizes[3];

    dim3 grid(SQ / BQ, B);
    fa_hmma<<<grid, 256>>>(Q, K, V, VL, O);
}